// round 1
// baseline (speedup 1.0000x reference)
#include <cuda_runtime.h>

#define T        2048
#define NT       256
#define VPT      8          // values per thread (NT*VPT == T)
#define PERIOD   24
#define HALF     12
#define DROP     11
#define NROWS    4085       // 4096 - DROP

// bank-conflict-avoiding pad: stride-8-per-thread becomes stride-9
#define PAD(i)   ((i) + ((i) >> 3))

__global__ __launch_bounds__(NT)
void seasonal_decomp_kernel(const float* __restrict__ x, float* __restrict__ out)
{
    __shared__ float cs[PAD(T) + 2];      // padded exclusive prefix sum, logical size T+1
    __shared__ float det[PAD(T - 1) + 1]; // padded detrended row, logical size T
    __shared__ float warp_tot[8];
    __shared__ float partial[192];
    __shared__ float pmean[PERIOD];

    const int tid  = threadIdx.x;
    const int lane = tid & 31;
    const int wid  = tid >> 5;
    const int row  = blockIdx.x + DROP;

    const float* __restrict__ xr = x + (size_t)row * T;

    // ---- load 8 contiguous values per thread (2x float4) ----
    float v[VPT];
    {
        float4 a = ((const float4*)xr)[tid * 2];
        float4 b = ((const float4*)xr)[tid * 2 + 1];
        v[0]=a.x; v[1]=a.y; v[2]=a.z; v[3]=a.w;
        v[4]=b.x; v[5]=b.y; v[6]=b.z; v[7]=b.w;
    }

    // ---- thread-local inclusive scan ----
    float incl[VPT];
    float s = 0.f;
#pragma unroll
    for (int j = 0; j < VPT; j++) { s += v[j]; incl[j] = s; }

    // ---- warp inclusive scan of per-thread totals ----
    float ws = s;
#pragma unroll
    for (int off = 1; off < 32; off <<= 1) {
        float t = __shfl_up_sync(0xffffffffu, ws, off);
        if (lane >= off) ws += t;
    }
    if (lane == 31) warp_tot[wid] = ws;
    float warp_excl = ws - s;
    __syncthreads();

    // ---- scan the 8 warp totals (threads 0..7) ----
    if (tid < 8) {
        float wt  = warp_tot[tid];
        float acc = wt;
#pragma unroll
        for (int off = 1; off < 8; off <<= 1) {
            float t = __shfl_up_sync(0x000000ffu, acc, off);
            if (tid >= off) acc += t;
        }
        warp_tot[tid] = acc - wt;   // exclusive prefix of warp totals
    }
    __syncthreads();

    // ---- write exclusive-cumsum array cs[0..T] (cs[i] = sum x[0..i-1]) ----
    float base = warp_tot[wid] + warp_excl;
#pragma unroll
    for (int j = 0; j < VPT; j++) {
        int i = tid * VPT + 1 + j;
        cs[PAD(i)] = base + incl[j];
    }
    if (tid == 0) cs[PAD(0)] = 0.f;
    __syncthreads();

    // ---- trend + detrended (registers), mirror detrended to smem ----
    float tr[VPT], dt[VPT];
#pragma unroll
    for (int j = 0; j < VPT; j++) {
        int t  = tid * VPT + j;
        int st = t - HALF;      if (st < 0) st = 0;
        int en = t + HALF + 1;  if (en > T) en = T;
        float sum = cs[PAD(en)] - cs[PAD(st)];
        tr[j] = sum / (float)(en - st);
        dt[j] = v[j] - tr[j];
        det[PAD(t)] = dt[j];
    }
    __syncthreads();

    // ---- phase partial sums: t = tid + 192*i covers all t, phase(t)=t%24 groups by tid%24 ----
    if (tid < 192) {
        float ps = 0.f;
        for (int t = tid; t < T; t += 192) ps += det[PAD(t)];
        partial[tid] = ps;
    }
    __syncthreads();

    // ---- reduce 8 partials per phase -> phase means ----
    if (tid < PERIOD) {
        float ps = 0.f;
#pragma unroll
        for (int k = 0; k < 8; k++) ps += partial[tid + PERIOD * k];
        int cnt = (T - tid + PERIOD - 1) / PERIOD;   // 86 for p<8, else 85
        pmean[tid] = ps / (float)cnt;
    }
    __syncthreads();

    // ---- pack (trend, seasonal, residual) for 8 t's -> 6x 128-bit stores ----
    union { float f[24]; float4 v4[6]; } o;
#pragma unroll
    for (int j = 0; j < VPT; j++) {
        int t = tid * VPT + j;
        float se = pmean[t % PERIOD];
        o.f[3 * j + 0] = tr[j];
        o.f[3 * j + 1] = se;
        o.f[3 * j + 2] = dt[j] - se;
    }
    float4* op = (float4*)(out + (size_t)blockIdx.x * (T * 3) + (size_t)tid * 24);
#pragma unroll
    for (int q = 0; q < 6; q++) op[q] = o.v4[q];
}

extern "C" void kernel_launch(void* const* d_in, const int* in_sizes, int n_in,
                              void* d_out, int out_size)
{
    const float* x = (const float*)d_in[0];
    float* out = (float*)d_out;
    seasonal_decomp_kernel<<<NROWS, NT>>>(x, out);
}

// round 2
// speedup vs baseline: 1.0083x; 1.0083x over previous
#include <cuda_runtime.h>

#define T        2048
#define NT       256
#define VPT      8          // values per thread (NT*VPT == T)
#define PERIOD   24
#define HALF     12
#define DROP     11
#define NROWS    4085       // 4096 - DROP

// bank-conflict-avoiding pad: stride-8-per-thread becomes stride-9
#define PAD(i)   ((i) + ((i) >> 3))

__global__ __launch_bounds__(NT)
void seasonal_decomp_kernel(const float* __restrict__ x, float* __restrict__ out)
{
    __shared__ float cs[PAD(T) + 2];      // padded exclusive prefix sum, logical size T+1
    __shared__ float det[PAD(T - 1) + 1]; // padded detrended row, logical size T
    __shared__ float warp_tot[8];
    __shared__ float partial[192];
    __shared__ float pmean[PERIOD];

    const int tid  = threadIdx.x;
    const int lane = tid & 31;
    const int wid  = tid >> 5;
    const int row  = blockIdx.x + DROP;

    const float* __restrict__ xr = x + (size_t)row * T;

    // ---- load 8 contiguous values per thread (2x float4) ----
    float v[VPT];
    {
        float4 a = ((const float4*)xr)[tid * 2];
        float4 b = ((const float4*)xr)[tid * 2 + 1];
        v[0]=a.x; v[1]=a.y; v[2]=a.z; v[3]=a.w;
        v[4]=b.x; v[5]=b.y; v[6]=b.z; v[7]=b.w;
    }

    // ---- thread-local inclusive scan ----
    float incl[VPT];
    float s = 0.f;
#pragma unroll
    for (int j = 0; j < VPT; j++) { s += v[j]; incl[j] = s; }

    // ---- warp inclusive scan of per-thread totals ----
    float ws = s;
#pragma unroll
    for (int off = 1; off < 32; off <<= 1) {
        float t = __shfl_up_sync(0xffffffffu, ws, off);
        if (lane >= off) ws += t;
    }
    if (lane == 31) warp_tot[wid] = ws;
    float warp_excl = ws - s;
    __syncthreads();

    // ---- scan the 8 warp totals (threads 0..7) ----
    if (tid < 8) {
        float wt  = warp_tot[tid];
        float acc = wt;
#pragma unroll
        for (int off = 1; off < 8; off <<= 1) {
            float t = __shfl_up_sync(0x000000ffu, acc, off);
            if (tid >= off) acc += t;
        }
        warp_tot[tid] = acc - wt;   // exclusive prefix of warp totals
    }
    __syncthreads();

    // ---- write exclusive-cumsum array cs[0..T] (cs[i] = sum x[0..i-1]) ----
    float base = warp_tot[wid] + warp_excl;
#pragma unroll
    for (int j = 0; j < VPT; j++) {
        int i = tid * VPT + 1 + j;
        cs[PAD(i)] = base + incl[j];
    }
    if (tid == 0) cs[PAD(0)] = 0.f;
    __syncthreads();

    // ---- trend + detrended (registers), mirror detrended to smem ----
    float tr[VPT], dt[VPT];
#pragma unroll
    for (int j = 0; j < VPT; j++) {
        int t  = tid * VPT + j;
        int st = t - HALF;      if (st < 0) st = 0;
        int en = t + HALF + 1;  if (en > T) en = T;
        float sum = cs[PAD(en)] - cs[PAD(st)];
        tr[j] = sum / (float)(en - st);
        dt[j] = v[j] - tr[j];
        det[PAD(t)] = dt[j];
    }
    __syncthreads();

    // ---- phase partial sums: t = tid + 192*i covers all t, phase(t)=t%24 groups by tid%24 ----
    if (tid < 192) {
        float ps = 0.f;
        for (int t = tid; t < T; t += 192) ps += det[PAD(t)];
        partial[tid] = ps;
    }
    __syncthreads();

    // ---- reduce 8 partials per phase -> phase means ----
    if (tid < PERIOD) {
        float ps = 0.f;
#pragma unroll
        for (int k = 0; k < 8; k++) ps += partial[tid + PERIOD * k];
        int cnt = (T - tid + PERIOD - 1) / PERIOD;   // 86 for p<8, else 85
        pmean[tid] = ps / (float)cnt;
    }
    __syncthreads();

    // ---- pack (trend, seasonal, residual) for 8 t's -> 6x 128-bit stores ----
    union { float f[24]; float4 v4[6]; } o;
#pragma unroll
    for (int j = 0; j < VPT; j++) {
        int t = tid * VPT + j;
        float se = pmean[t % PERIOD];
        o.f[3 * j + 0] = tr[j];
        o.f[3 * j + 1] = se;
        o.f[3 * j + 2] = dt[j] - se;
    }
    float4* op = (float4*)(out + (size_t)blockIdx.x * (T * 3) + (size_t)tid * 24);
#pragma unroll
    for (int q = 0; q < 6; q++) op[q] = o.v4[q];
}

extern "C" void kernel_launch(void* const* d_in, const int* in_sizes, int n_in,
                              void* d_out, int out_size)
{
    const float* x = (const float*)d_in[0];
    float* out = (float*)d_out;
    seasonal_decomp_kernel<<<NROWS, NT>>>(x, out);
}